// round 6
// baseline (speedup 1.0000x reference)
#include <cuda_runtime.h>
#include <cuda_bf16.h>

// Problem shape (fixed by the dataset): B=64 segments, L=2048 tokens each,
// N=131072 tokens, D=512 features. Output = [B*D] means ++ [N] attn weights.
#define SEG_B   64
#define FEAT_D  512
#define D4      (FEAT_D / 4)     // 128 float4 lanes
#define SPLIT   16               // row-chunks per segment (halved vs R5)
#define TPB     128              // one thread per float4 column lane

// Phase-1 partial sums: [B][SPLIT][D] floats = 2 MB scratch.
__device__ float g_partials[SEG_B * SPLIT * FEAT_D];

// ---------------------------------------------------------------------------
// lengths may be int32 (JAX x64 disabled) or int64 (as declared). Detect by
// checking whether the int32 interpretation sums to the total token count.
// ---------------------------------------------------------------------------
__device__ __forceinline__ bool lengths_are_i64(const void* lengths, long long n_total)
{
    const int* p32 = (const int*)lengths;
    long long s = 0;
    #pragma unroll 8
    for (int i = 0; i < SEG_B; ++i) s += p32[i];
    return s != n_total;
}

__device__ __forceinline__ long long len_at(const void* lengths, int i, bool is64)
{
    return is64 ? ((const long long*)lengths)[i]
                : (long long)((const int*)lengths)[i];
}

// ---------------------------------------------------------------------------
// Phase 1: each block = (segment b, row-chunk c). Accumulate chunk_rows rows
// of 512 floats into a per-thread float4 register accumulator, store partial
// to scratch. Also writes attn_weights = 1/len for the rows this block owns.
// ---------------------------------------------------------------------------
__global__ void __launch_bounds__(TPB)
mean_pool_partial(const float* __restrict__ x,
                  const void* __restrict__ lengths,
                  float* __restrict__ attn,
                  long long n_total)
{
    const int b     = blockIdx.y;
    const int chunk = blockIdx.x;
    const int t     = threadIdx.x;           // float4 lane 0..127

    __shared__ long long s_start;
    __shared__ int       s_len;
    if (t == 0) {
        const bool is64 = lengths_are_i64(lengths, n_total);
        long long st = 0;
        for (int i = 0; i < SEG_B; ++i) {
            long long li = len_at(lengths, i, is64);
            if (i < b) st += li;
            if (i == b) s_len = (int)li;
        }
        s_start = st;
    }
    __syncthreads();

    const long long seg_start = s_start;
    const int len        = s_len;
    const int chunk_rows = (len + SPLIT - 1) / SPLIT;
    const int r0         = chunk * chunk_rows;
    const int r1         = min(r0 + chunk_rows, len);
    const int rows       = max(r1 - r0, 0);

    const float4* __restrict__ xr =
        reinterpret_cast<const float4*>(x) + (seg_start + r0) * (long long)D4;

    // Two independent accumulators + 8-deep unroll: 8 outstanding LDG.128
    // per thread per iteration for DRAM latency hiding (MLP).
    float4 acc0 = make_float4(0.f, 0.f, 0.f, 0.f);
    float4 acc1 = make_float4(0.f, 0.f, 0.f, 0.f);

    int r = 0;
    for (; r + 8 <= rows; r += 8) {
        float4 a0 = xr[(long long)(r + 0) * D4 + t];
        float4 a1 = xr[(long long)(r + 1) * D4 + t];
        float4 a2 = xr[(long long)(r + 2) * D4 + t];
        float4 a3 = xr[(long long)(r + 3) * D4 + t];
        float4 a4 = xr[(long long)(r + 4) * D4 + t];
        float4 a5 = xr[(long long)(r + 5) * D4 + t];
        float4 a6 = xr[(long long)(r + 6) * D4 + t];
        float4 a7 = xr[(long long)(r + 7) * D4 + t];
        acc0.x += (a0.x + a1.x) + (a2.x + a3.x);
        acc0.y += (a0.y + a1.y) + (a2.y + a3.y);
        acc0.z += (a0.z + a1.z) + (a2.z + a3.z);
        acc0.w += (a0.w + a1.w) + (a2.w + a3.w);
        acc1.x += (a4.x + a5.x) + (a6.x + a7.x);
        acc1.y += (a4.y + a5.y) + (a6.y + a7.y);
        acc1.z += (a4.z + a5.z) + (a6.z + a7.z);
        acc1.w += (a4.w + a5.w) + (a6.w + a7.w);
    }
    for (; r < rows; ++r) {
        float4 a = xr[(long long)r * D4 + t];
        acc0.x += a.x; acc0.y += a.y; acc0.z += a.z; acc0.w += a.w;
    }
    acc0.x += acc1.x; acc0.y += acc1.y; acc0.z += acc1.z; acc0.w += acc1.w;

    float4* __restrict__ sp =
        reinterpret_cast<float4*>(g_partials) + (b * SPLIT + chunk) * D4;
    sp[t] = acc0;

    // attn weights for the rows this block owns
    const float inv = 1.0f / (float)len;
    for (int rr = t; rr < rows; rr += TPB)
        attn[seg_start + r0 + rr] = inv;
}

// ---------------------------------------------------------------------------
// Phase 2: grid (4, B); each block covers 128 scalar columns of one segment,
// each thread sums SPLIT partials for its column, scales by 1/len, writes out.
// Coalesced: consecutive threads -> consecutive addresses at every step.
// ---------------------------------------------------------------------------
__global__ void __launch_bounds__(TPB)
mean_pool_reduce(const void* __restrict__ lengths,
                 float* __restrict__ out,
                 long long n_total)
{
    const int b   = blockIdx.y;
    const int col = blockIdx.x * TPB + threadIdx.x;   // 0..511 scalar column

    const float* __restrict__ sp = g_partials + (b * SPLIT) * FEAT_D + col;

    float acc = 0.f;
    #pragma unroll
    for (int c = 0; c < SPLIT; ++c)
        acc += sp[c * FEAT_D];

    __shared__ bool s_is64;
    if (threadIdx.x == 0) s_is64 = lengths_are_i64(lengths, n_total);
    __syncthreads();

    const float inv = 1.0f / (float)len_at(lengths, b, s_is64);
    out[b * FEAT_D + col] = acc * inv;
}

extern "C" void kernel_launch(void* const* d_in, const int* in_sizes, int n_in,
                              void* d_out, int out_size)
{
    const float* x       = (const float*)d_in[0];
    const void*  lengths = d_in[1];

    const long long n_total = (long long)in_sizes[0] / FEAT_D;

    float* out  = (float*)d_out;                 // [B, D] means first
    float* attn = out + SEG_B * FEAT_D;          // [N] attention weights

    dim3 grid1(SPLIT, SEG_B);
    mean_pool_partial<<<grid1, TPB>>>(x, lengths, attn, n_total);

    dim3 grid2(FEAT_D / TPB, SEG_B);
    mean_pool_reduce<<<grid2, TPB>>>(lengths, out, n_total);
}

// round 7
// speedup vs baseline: 1.0464x; 1.0464x over previous
#include <cuda_runtime.h>
#include <cuda_bf16.h>

// Problem shape (fixed by the dataset): B=64 segments, L=2048 tokens each,
// N=131072 tokens, D=512 features. Output = [B*D] means ++ [N] attn weights.
#define SEG_B   64
#define FEAT_D  512
#define D4      (FEAT_D / 4)     // 128 float4 lanes
#define SPLIT   32               // row-chunks per segment (R5 config)
#define TPB     128              // one thread per float4 column lane

// Phase-1 partial sums: [B][SPLIT][D] floats = 4 MB scratch.
__device__ float g_partials[SEG_B * SPLIT * FEAT_D];
// Per-segment completion counters (zero-initialized; reducer resets to 0
// each launch, so graph replays see a clean state).
__device__ unsigned int g_done[SEG_B];

// ---------------------------------------------------------------------------
// lengths may be int32 (JAX x64 disabled) or int64 (as declared). Detect by
// checking whether the int32 interpretation sums to the total token count.
// ---------------------------------------------------------------------------
__device__ __forceinline__ bool lengths_are_i64(const void* lengths, long long n_total)
{
    const int* p32 = (const int*)lengths;
    long long s = 0;
    #pragma unroll 8
    for (int i = 0; i < SEG_B; ++i) s += p32[i];
    return s != n_total;
}

__device__ __forceinline__ long long len_at(const void* lengths, int i, bool is64)
{
    return is64 ? ((const long long*)lengths)[i]
                : (long long)((const int*)lengths)[i];
}

// ---------------------------------------------------------------------------
// Single fused kernel: each block = (segment b, row-chunk c).
//  1) accumulate its row-chunk into a per-thread float4 register accumulator
//  2) store the partial to scratch, write attn weights for its rows
//  3) last block to finish for segment b reduces the SPLIT partials and
//     writes the [D] mean for that segment (threadfence-reduction pattern).
// Exactly one block reduces each segment, in fixed order -> deterministic.
// ---------------------------------------------------------------------------
__global__ void __launch_bounds__(TPB)
mean_pool_fused(const float* __restrict__ x,
                const void* __restrict__ lengths,
                float* __restrict__ out,
                float* __restrict__ attn,
                long long n_total)
{
    const int b     = blockIdx.y;
    const int chunk = blockIdx.x;
    const int t     = threadIdx.x;           // float4 lane 0..127

    __shared__ long long s_start;
    __shared__ int       s_len;
    if (t == 0) {
        const bool is64 = lengths_are_i64(lengths, n_total);
        long long st = 0;
        for (int i = 0; i < SEG_B; ++i) {
            long long li = len_at(lengths, i, is64);
            if (i < b) st += li;
            if (i == b) s_len = (int)li;
        }
        s_start = st;
    }
    __syncthreads();

    const long long seg_start = s_start;
    const int len        = s_len;
    const int chunk_rows = (len + SPLIT - 1) / SPLIT;
    const int r0         = chunk * chunk_rows;
    const int r1         = min(r0 + chunk_rows, len);
    const int rows       = max(r1 - r0, 0);

    const float4* __restrict__ xr =
        reinterpret_cast<const float4*>(x) + (seg_start + r0) * (long long)D4;

    float4 acc = make_float4(0.f, 0.f, 0.f, 0.f);

    int r = 0;
    for (; r + 4 <= rows; r += 4) {
        float4 a0 = xr[(long long)(r + 0) * D4 + t];
        float4 a1 = xr[(long long)(r + 1) * D4 + t];
        float4 a2 = xr[(long long)(r + 2) * D4 + t];
        float4 a3 = xr[(long long)(r + 3) * D4 + t];
        acc.x += (a0.x + a1.x) + (a2.x + a3.x);
        acc.y += (a0.y + a1.y) + (a2.y + a3.y);
        acc.z += (a0.z + a1.z) + (a2.z + a3.z);
        acc.w += (a0.w + a1.w) + (a2.w + a3.w);
    }
    for (; r < rows; ++r) {
        float4 a = xr[(long long)r * D4 + t];
        acc.x += a.x; acc.y += a.y; acc.z += a.z; acc.w += a.w;
    }

    float4* __restrict__ sp =
        reinterpret_cast<float4*>(g_partials) + (b * SPLIT + chunk) * D4;
    sp[t] = acc;

    // attn weights for the rows this block owns
    const float inv = 1.0f / (float)len;
    for (int rr = t; rr < rows; rr += TPB)
        attn[seg_start + r0 + rr] = inv;

    // ---- last-block-done reduction for this segment ----
    __threadfence();                         // make partial visible (release)
    __shared__ bool s_last;
    if (t == 0) {
        unsigned int prev = atomicAdd(&g_done[b], 1u);
        s_last = (prev == SPLIT - 1);
    }
    __syncthreads();

    if (s_last) {
        __threadfence();                     // acquire: see all partials

        const float4* __restrict__ base =
            reinterpret_cast<const float4*>(g_partials) + b * SPLIT * D4;

        float4 sum = make_float4(0.f, 0.f, 0.f, 0.f);
        #pragma unroll
        for (int c = 0; c < SPLIT; ++c) {
            float4 a = base[c * D4 + t];
            sum.x += a.x; sum.y += a.y; sum.z += a.z; sum.w += a.w;
        }
        sum.x *= inv; sum.y *= inv; sum.z *= inv; sum.w *= inv;
        reinterpret_cast<float4*>(out)[b * D4 + t] = sum;

        if (t == 0) g_done[b] = 0;           // reset for next graph replay
    }
}

extern "C" void kernel_launch(void* const* d_in, const int* in_sizes, int n_in,
                              void* d_out, int out_size)
{
    const float* x       = (const float*)d_in[0];
    const void*  lengths = d_in[1];

    const long long n_total = (long long)in_sizes[0] / FEAT_D;

    float* out  = (float*)d_out;                 // [B, D] means first
    float* attn = out + SEG_B * FEAT_D;          // [N] attention weights

    dim3 grid(SPLIT, SEG_B);
    mean_pool_fused<<<grid, TPB>>>(x, lengths, out, attn, n_total);
}